// round 14
// baseline (speedup 1.0000x reference)
#include <cuda_runtime.h>
#include <cuda_bf16.h>
#include <cstdint>
#include <cstddef>

#define T_TOK 8192
#define D_DIM 4096
#define I_DIM 11008

// ---------------- device scratch (static, no allocs) ----------------
// Quantized operands stored as INTEGER-VALUED bf16 (exact for |v|<=127).
__device__ __align__(16) __nv_bfloat16 g_Wgb[(size_t)I_DIM * D_DIM];
__device__ __align__(16) __nv_bfloat16 g_Wub[(size_t)I_DIM * D_DIM];
__device__ __align__(16) __nv_bfloat16 g_Wdb[(size_t)D_DIM * I_DIM];
__device__ float g_wsg[I_DIM];
__device__ float g_wsu[I_DIM];
__device__ float g_wsd[D_DIM];
__device__ __align__(16) __nv_bfloat16 g_qb[(size_t)T_TOK * D_DIM];
__device__ float g_s[T_TOK];
__device__ __align__(16) float g_h[(size_t)T_TOK * I_DIM];
__device__ unsigned g_hamax[T_TOK];
__device__ __align__(16) __nv_bfloat16 g_q2b[(size_t)T_TOK * I_DIM];
__device__ float g_s2[T_TOK];

// ---------------- small helpers ----------------
__device__ __forceinline__ float warp_sum(float v) {
#pragma unroll
    for (int o = 16; o; o >>= 1) v += __shfl_xor_sync(0xffffffffu, v, o);
    return v;
}
__device__ __forceinline__ float warp_max(float v) {
#pragma unroll
    for (int o = 16; o; o >>= 1) v = fmaxf(v, __shfl_xor_sync(0xffffffffu, v, o));
    return v;
}
__device__ __forceinline__ float block_sum(float v, float* red) {
    v = warp_sum(v);
    __syncthreads();
    if ((threadIdx.x & 31) == 0) red[threadIdx.x >> 5] = v;
    __syncthreads();
    float r = red[0];
#pragma unroll
    for (int i = 1; i < 8; i++) r += red[i];
    return r;
}
__device__ __forceinline__ float block_max(float v, float* red) {
    v = warp_max(v);
    __syncthreads();
    if ((threadIdx.x & 31) == 0) red[threadIdx.x >> 5] = v;
    __syncthreads();
    float r = red[0];
#pragma unroll
    for (int i = 1; i < 8; i++) r = fmaxf(r, red[i]);
    return r;
}

__device__ __forceinline__ int qint(float x, float s) {
    return max(-127, min(127, __float2int_rn(x / s)));
}
// quantize 2 floats -> packed bf16x2 (integer-valued, exact)
__device__ __forceinline__ uint32_t qpair(float a, float b, float s) {
    __nv_bfloat162 p = __floats2bfloat162_rn((float)qint(a, s), (float)qint(b, s));
    return *(uint32_t*)&p;
}
__device__ __forceinline__ float silu_f(float x) {
    return x / (1.0f + expf(-x));
}

// ---------------- async copy / mma primitives ----------------
__device__ __forceinline__ void cp_async16(uint32_t dst, const void* src) {
    asm volatile("cp.async.cg.shared.global [%0], [%1], 16;\n" :: "r"(dst), "l"(src));
}
__device__ __forceinline__ void cp_commit() { asm volatile("cp.async.commit_group;\n"); }
template <int N> __device__ __forceinline__ void cp_wait() {
    asm volatile("cp.async.wait_group %0;\n" :: "n"(N));
}
__device__ __forceinline__ void ldm_x4(uint32_t addr, uint32_t r[4]) {
    asm volatile("ldmatrix.sync.aligned.m8n8.x4.shared.b16 {%0,%1,%2,%3}, [%4];\n"
                 : "=r"(r[0]), "=r"(r[1]), "=r"(r[2]), "=r"(r[3]) : "r"(addr));
}
__device__ __forceinline__ void mma_bf16(float c[4], const uint32_t a[4],
                                         uint32_t b0, uint32_t b1) {
    asm volatile(
        "mma.sync.aligned.m16n8k16.row.col.f32.bf16.bf16.f32 "
        "{%0,%1,%2,%3}, {%4,%5,%6,%7}, {%8,%9}, {%0,%1,%2,%3};\n"
        : "+f"(c[0]), "+f"(c[1]), "+f"(c[2]), "+f"(c[3])
        : "r"(a[0]), "r"(a[1]), "r"(a[2]), "r"(a[3]), "r"(b0), "r"(b1));
}

// smem tile: rows of 128 bytes (64 bf16); 16B chunk swizzle c' = c ^ (row & 7)
__device__ __forceinline__ uint32_t sw_off(int row, int c) {
    return (uint32_t)(row * 128 + ((c ^ (row & 7)) << 4));
}
// A fragment (16 rows x 16 bf16) via ldmatrix.x4; ks = k16-step within 64-col tile
__device__ __forceinline__ void lda_frag(uint32_t tb, int Rb, int ks, uint32_t a[4]) {
    int L = threadIdx.x & 31;
    int g4 = L >> 3;
    int row = Rb + ((g4 & 1) << 3) + (L & 7);
    int c = 2 * ks + (g4 >> 1);
    ldm_x4(tb + sw_off(row, c), a);
}
// B pair: two 8xk16 n-tiles -> {b0(nt), b1(nt), b0(nt+1), b1(nt+1)}
__device__ __forceinline__ void ldb_pair(uint32_t tb, int Nb, int ks, uint32_t b[4]) {
    int L = threadIdx.x & 31;
    int g4 = L >> 3;
    int row = Nb + ((g4 >> 1) << 3) + (L & 7);
    int c = 2 * ks + (g4 & 1);
    ldm_x4(tb + sw_off(row, c), b);
}

// ---------------- quantization kernels (emit integer-valued bf16) ----------------
// Row cached in registers between amax pass and quantize pass (single global read).
template <int WHICH>
__global__ void quant_w_kernel(const float* __restrict__ W) {
    __shared__ float red[8];
    __nv_bfloat16* Wq; float* ws;
    if (WHICH == 0) { Wq = g_Wgb; ws = g_wsg; }
    else if (WHICH == 1) { Wq = g_Wub; ws = g_wsu; }
    else { Wq = g_Wdb; ws = g_wsd; }
    const int rowlen = (WHICH == 2) ? I_DIM : D_DIM;
    const int nch = rowlen >> 2;                 // 1024 or 2752
    const int PER = (WHICH == 2) ? 11 : 4;       // chunks per thread (256 thr)

    int row = blockIdx.x;
    const float4* W4 = (const float4*)(W + (size_t)row * rowlen);
    float4 v[11];
    float amax = 0.0f;
#pragma unroll
    for (int k = 0; k < PER; k++) {
        int c = threadIdx.x + k * 256;
        if (c < nch) {
            v[k] = W4[c];
            amax = fmaxf(amax, fmaxf(fmaxf(fabsf(v[k].x), fabsf(v[k].y)),
                                     fmaxf(fabsf(v[k].z), fabsf(v[k].w))));
        }
    }
    amax = block_max(amax, red);
    float s = fmaxf(amax / 127.0f, 1e-8f);
    if (threadIdx.x == 0) ws[row] = s;
    uint2* Q2 = (uint2*)(Wq + (size_t)row * rowlen);
#pragma unroll
    for (int k = 0; k < PER; k++) {
        int c = threadIdx.x + k * 256;
        if (c < nch)
            Q2[c] = make_uint2(qpair(v[k].x, v[k].y, s), qpair(v[k].z, v[k].w, s));
    }
}

__global__ void rmsnorm_quant_kernel(const float* __restrict__ X, const float* __restrict__ gw) {
    __shared__ float red[8];
    int t = blockIdx.x;
    if (threadIdx.x == 0) g_hamax[t] = 0u;  // reset for gateup epilogue atomics
    const float4* X4 = (const float4*)(X + (size_t)t * D_DIM);
    const float4* W4 = (const float4*)gw;
    float4 xv[4], wv[4];
    float ss = 0.0f;
#pragma unroll
    for (int k = 0; k < 4; k++) {
        int c = threadIdx.x + k * 256;
        xv[k] = X4[c];
        wv[k] = W4[c];
        ss += xv[k].x * xv[k].x + xv[k].y * xv[k].y + xv[k].z * xv[k].z + xv[k].w * xv[k].w;
    }
    ss = block_sum(ss, red);
    float rinv = rsqrtf(ss / (float)D_DIM + 1e-6f);
    float4 vv[4];
    float amax = 0.0f;
#pragma unroll
    for (int k = 0; k < 4; k++) {
        vv[k].x = xv[k].x * rinv * wv[k].x;
        vv[k].y = xv[k].y * rinv * wv[k].y;
        vv[k].z = xv[k].z * rinv * wv[k].z;
        vv[k].w = xv[k].w * rinv * wv[k].w;
        amax = fmaxf(amax, fmaxf(fmaxf(fabsf(vv[k].x), fabsf(vv[k].y)),
                                 fmaxf(fabsf(vv[k].z), fabsf(vv[k].w))));
    }
    amax = block_max(amax, red);
    float s = fmaxf(amax / 127.0f, 1e-8f);
    if (threadIdx.x == 0) g_s[t] = s;
    uint2* Q2 = (uint2*)(g_qb + (size_t)t * D_DIM);
#pragma unroll
    for (int k = 0; k < 4; k++) {
        float4 v = vv[k];
        Q2[threadIdx.x + k * 256] = make_uint2(qpair(v.x, v.y, s), qpair(v.z, v.w, s));
    }
}

// amax precomputed by gateup epilogue atomics -> single pass over h
__global__ void quant_h_kernel() {
    int t = blockIdx.x;
    float amax = __uint_as_float(g_hamax[t]);
    float s = fmaxf(amax / 127.0f, 1e-8f);
    if (threadIdx.x == 0) g_s2[t] = s;
    const float4* H4 = (const float4*)(g_h + (size_t)t * I_DIM);
    uint2* Q2 = (uint2*)(g_q2b + (size_t)t * I_DIM);
    const int nch = I_DIM >> 2;  // 2752
    for (int c = threadIdx.x; c < nch; c += 256) {
        float4 v = H4[c];
        Q2[c] = make_uint2(qpair(v.x, v.y, s), qpair(v.z, v.w, s));
    }
}

// ---------------- GEMM 1: gate/up fused, SwiGLU epilogue -> g_h ----------------
// Block tile 128x128, K-slab 128 bf16 (two 64-col sub-tiles), 8 warps (4m x 2n),
// warp tile 32x64 for BOTH gate and up, 2 stages x 96KB, 256 threads.
// Sub-tile layout within a stage: [A0 16K][A1 16K][Bg0][Bg1][Bu0][Bu1].
#define GU_SUB   16384
#define GU_STAGE (6 * GU_SUB)   // 96 KB
#define GU_NSTG  2
#define GU_SMEM  (GU_NSTG * GU_STAGE)

__global__ __launch_bounds__(256, 1) void gemm_gateup_kernel() {
    extern __shared__ __align__(128) int8_t sm[];
    const int tid = threadIdx.x;
    const int lane = tid & 31;
    const int wid = tid >> 5;
    const int wm = wid >> 1;  // 0..3
    const int wn = wid & 1;   // 0..1
    const int by = blockIdx.x;  // T tile (64) fast -> weight L2 reuse
    const int bx = blockIdx.y;  // I tile (86)
    const uint32_t smbase = (uint32_t)__cvta_generic_to_shared(sm);

    float accg[2][8][4];
    float accu[2][8][4];
#pragma unroll
    for (int a = 0; a < 2; a++)
#pragma unroll
        for (int b = 0; b < 8; b++)
#pragma unroll
            for (int c = 0; c < 4; c++) { accg[a][b][c] = 0.0f; accu[a][b][c] = 0.0f; }

    // One K-slab = 128 bf16 = two 64-col sub-tiles per operand.
    auto load_stage = [&](int stage, int kt) {
        const size_t k0 = (size_t)kt * 128;
#pragma unroll
        for (int j = 0; j < 24; j++) {
            int cid = tid + j * 256;      // 0..6143
            int sub = cid >> 10;          // 0..5: A0 A1 Bg0 Bg1 Bu0 Bu1
            int q = cid & 1023;
            int row = q >> 3, c = q & 7;
            uint32_t dst = smbase + stage * GU_STAGE + sub * GU_SUB + sw_off(row, c);
            int khalf = (sub & 1) * 64;
            const __nv_bfloat16* src;
            if (sub < 2)      src = g_qb  + (size_t)(by * 128 + row) * D_DIM + k0 + khalf + c * 8;
            else if (sub < 4) src = g_Wgb + (size_t)(bx * 128 + row) * D_DIM + k0 + khalf + c * 8;
            else              src = g_Wub + (size_t)(bx * 128 + row) * D_DIM + k0 + khalf + c * 8;
            cp_async16(dst, src);
        }
    };

    load_stage(0, 0); cp_commit();

    const int KT = D_DIM / 128;  // 32
    for (int kt = 0; kt < KT; kt++) {
        cp_wait<0>();
        __syncthreads();
        if (kt + 1 < KT) { load_stage((kt + 1) & 1, kt + 1); cp_commit(); }

        uint32_t st = smbase + (kt & 1) * GU_STAGE;
#pragma unroll
        for (int kss = 0; kss < 8; kss++) {       // 8 k16-steps per slab
            int half = kss >> 2;                  // sub-tile index
            int ks = kss & 3;                     // k16 within sub-tile
            uint32_t ta  = st + half * GU_SUB;
            uint32_t tbg = st + (2 + half) * GU_SUB;
            uint32_t tbu = st + (4 + half) * GU_SUB;
            uint32_t a[2][4];
            lda_frag(ta, wm * 32,      ks, a[0]);
            lda_frag(ta, wm * 32 + 16, ks, a[1]);
#pragma unroll
            for (int j = 0; j < 4; j++) {
                uint32_t bg[4], bu[4];
                ldb_pair(tbg, wn * 64 + j * 16, ks, bg);
                ldb_pair(tbu, wn * 64 + j * 16, ks, bu);
#pragma unroll
                for (int mt = 0; mt < 2; mt++) {
                    mma_bf16(accg[mt][2 * j],     a[mt], bg[0], bg[1]);
                    mma_bf16(accg[mt][2 * j + 1], a[mt], bg[2], bg[3]);
                    mma_bf16(accu[mt][2 * j],     a[mt], bu[0], bu[1]);
                    mma_bf16(accu[mt][2 * j + 1], a[mt], bu[2], bu[3]);
                }
            }
        }
    }

    // epilogue: dequant, SwiGLU, store h (fp32), per-token amax atomic
    const int g = lane >> 2, tg = lane & 3;
#pragma unroll
    for (int mt = 0; mt < 2; mt++) {
        int t0 = by * 128 + wm * 32 + mt * 16 + g;
        float s0 = g_s[t0];
        float s1 = g_s[t0 + 8];
        float m0 = 0.0f, m1 = 0.0f;
#pragma unroll
        for (int nt = 0; nt < 8; nt++) {
            int i0 = bx * 128 + wn * 64 + nt * 8 + tg * 2;
            float wg0 = g_wsg[i0], wg1 = g_wsg[i0 + 1];
            float wu0 = g_wsu[i0], wu1 = g_wsu[i0 + 1];
            float ga = accg[mt][nt][0] * s0 * wg0;
            float gb = accg[mt][nt][1] * s0 * wg1;
            float gc = accg[mt][nt][2] * s1 * wg0;
            float gd = accg[mt][nt][3] * s1 * wg1;
            float ua = accu[mt][nt][0] * s0 * wu0;
            float ub = accu[mt][nt][1] * s0 * wu1;
            float uc = accu[mt][nt][2] * s1 * wu0;
            float ud = accu[mt][nt][3] * s1 * wu1;
            float2 r0 = make_float2(silu_f(ga) * ua, silu_f(gb) * ub);
            float2 r1 = make_float2(silu_f(gc) * uc, silu_f(gd) * ud);
            m0 = fmaxf(m0, fmaxf(fabsf(r0.x), fabsf(r0.y)));
            m1 = fmaxf(m1, fmaxf(fabsf(r1.x), fabsf(r1.y)));
            *(float2*)(g_h + (size_t)t0 * I_DIM + i0)       = r0;
            *(float2*)(g_h + (size_t)(t0 + 8) * I_DIM + i0) = r1;
        }
        m0 = fmaxf(m0, __shfl_xor_sync(0xffffffffu, m0, 1));
        m0 = fmaxf(m0, __shfl_xor_sync(0xffffffffu, m0, 2));
        m1 = fmaxf(m1, __shfl_xor_sync(0xffffffffu, m1, 1));
        m1 = fmaxf(m1, __shfl_xor_sync(0xffffffffu, m1, 2));
        if (tg == 0) {
            atomicMax(&g_hamax[t0],     __float_as_uint(m0));
            atomicMax(&g_hamax[t0 + 8], __float_as_uint(m1));
        }
    }
}

// ---------------- GEMM 2: down proj -> d_out ----------------
// Block 128x128, K-slab 128 bf16 (two 64-col sub-tiles), 8 warps (4m x 2n),
// warp tile 32x64, 2 stages x 64KB ([A0][A1][B0][B1]), 1 CTA/SM, 256 threads.
// Mirrors the proven gateup mainloop; barriers per CTA: 172 -> 86.
#define DN_SUB   16384
#define DN_STAGE (4 * DN_SUB)   // 64 KB
#define DN_NSTG  2
#define DN_SMEM  (DN_NSTG * DN_STAGE)

__global__ __launch_bounds__(256, 1) void gemm_down_kernel(float* __restrict__ out) {
    extern __shared__ __align__(128) int8_t sm[];
    const int tid = threadIdx.x;
    const int lane = tid & 31;
    const int wid = tid >> 5;
    const int wm = wid >> 1;  // 0..3
    const int wn = wid & 1;   // 0..1
    const int by = blockIdx.x;  // T tile (64) fast
    const int bx = blockIdx.y;  // D tile (32)
    const uint32_t smbase = (uint32_t)__cvta_generic_to_shared(sm);

    float acc[2][8][4];
#pragma unroll
    for (int a = 0; a < 2; a++)
#pragma unroll
        for (int b = 0; b < 8; b++)
#pragma unroll
            for (int c = 0; c < 4; c++) acc[a][b][c] = 0.0f;

    // One K-slab = 128 bf16 = two 64-col sub-tiles per operand.
    auto load_stage = [&](int stage, int kt) {
        const size_t k0 = (size_t)kt * 128;
#pragma unroll
        for (int j = 0; j < 16; j++) {
            int cid = tid + j * 256;      // 0..4095
            int sub = cid >> 10;          // 0..3: A0 A1 B0 B1
            int q = cid & 1023;
            int row = q >> 3, c = q & 7;
            uint32_t dst = smbase + stage * DN_STAGE + sub * DN_SUB + sw_off(row, c);
            int khalf = (sub & 1) * 64;
            const __nv_bfloat16* src;
            if (sub < 2) src = g_q2b + (size_t)(by * 128 + row) * I_DIM + k0 + khalf + c * 8;
            else         src = g_Wdb + (size_t)(bx * 128 + row) * I_DIM + k0 + khalf + c * 8;
            cp_async16(dst, src);
        }
    };

    load_stage(0, 0); cp_commit();

    const int KT = I_DIM / 128;  // 86
    for (int kt = 0; kt < KT; kt++) {
        cp_wait<0>();
        __syncthreads();
        if (kt + 1 < KT) { load_stage((kt + 1) & 1, kt + 1); cp_commit(); }

        uint32_t st = smbase + (kt & 1) * DN_STAGE;
#pragma unroll
        for (int kss = 0; kss < 8; kss++) {       // 8 k16-steps per slab
            int half = kss >> 2;
            int ks = kss & 3;
            uint32_t ta  = st + half * DN_SUB;
            uint32_t tbb = st + (2 + half) * DN_SUB;
            uint32_t a[2][4];
            lda_frag(ta, wm * 32,      ks, a[0]);
            lda_frag(ta, wm * 32 + 16, ks, a[1]);
#pragma unroll
            for (int j = 0; j < 4; j++) {
                uint32_t bb[4];
                ldb_pair(tbb, wn * 64 + j * 16, ks, bb);
#pragma unroll
                for (int mt = 0; mt < 2; mt++) {
                    mma_bf16(acc[mt][2 * j],     a[mt], bb[0], bb[1]);
                    mma_bf16(acc[mt][2 * j + 1], a[mt], bb[2], bb[3]);
                }
            }
        }
    }

    const int g = lane >> 2, tg = lane & 3;
#pragma unroll
    for (int mt = 0; mt < 2; mt++) {
        int t0 = by * 128 + wm * 32 + mt * 16 + g;
        float s0 = g_s2[t0];
        float s1 = g_s2[t0 + 8];
#pragma unroll
        for (int nt = 0; nt < 8; nt++) {
            int d0 = bx * 128 + wn * 64 + nt * 8 + tg * 2;
            float w0 = g_wsd[d0], w1 = g_wsd[d0 + 1];
            float2 r0 = make_float2(acc[mt][nt][0] * s0 * w0,
                                    acc[mt][nt][1] * s0 * w1);
            float2 r1 = make_float2(acc[mt][nt][2] * s1 * w0,
                                    acc[mt][nt][3] * s1 * w1);
            *(float2*)(out + (size_t)t0 * D_DIM + d0)       = r0;
            *(float2*)(out + (size_t)(t0 + 8) * D_DIM + d0) = r1;
        }
    }
}

// ---------------- launch ----------------
extern "C" void kernel_launch(void* const* d_in, const int* in_sizes, int n_in,
                              void* d_out, int out_size) {
    const float* X  = (const float*)d_in[0];  // hidden_states [4,2048,4096]
    const float* gw = (const float*)d_in[1];  // rmsnorm_weight [4096]
    const float* Wg = (const float*)d_in[2];  // [11008,4096]
    const float* Wu = (const float*)d_in[3];  // [11008,4096]
    const float* Wd = (const float*)d_in[4];  // [4096,11008]
    float* out = (float*)d_out;

    static cudaStream_t s2 = nullptr;
    static cudaEvent_t evF = nullptr, evD = nullptr;
    if (s2 == nullptr) {
        cudaFuncSetAttribute(gemm_gateup_kernel, cudaFuncAttributeMaxDynamicSharedMemorySize, GU_SMEM);
        cudaFuncSetAttribute(gemm_down_kernel,   cudaFuncAttributeMaxDynamicSharedMemorySize, DN_SMEM);
        cudaStreamCreateWithFlags(&s2, cudaStreamNonBlocking);
        cudaEventCreateWithFlags(&evF, cudaEventDisableTiming);
        cudaEventCreateWithFlags(&evD, cudaEventDisableTiming);
    }

    // Front (main stream): weight quant for gate/up + rmsnorm activation quant.
    quant_w_kernel<0><<<I_DIM, 256>>>(Wg);
    quant_w_kernel<1><<<I_DIM, 256>>>(Wu);
    rmsnorm_quant_kernel<<<T_TOK, 256>>>(X, gw);

    // Fork: Wd quantization on side stream, concurrent with gateup GEMM.
    cudaEventRecord(evF, 0);
    cudaStreamWaitEvent(s2, evF, 0);
    quant_w_kernel<2><<<D_DIM, 256, 0, s2>>>(Wd);
    cudaEventRecord(evD, s2);

    // Gateup GEMM (proven R8 config) + quant_h on main stream.
    gemm_gateup_kernel<<<dim3(T_TOK / 128, I_DIM / 128), 256, GU_SMEM>>>();
    quant_h_kernel<<<T_TOK, 256>>>();

    // Join: down GEMM needs both q2 (main) and quantized Wd (side stream).
    cudaStreamWaitEvent(0, evD, 0);
    gemm_down_kernel<<<dim3(T_TOK / 128, D_DIM / 128), 256, DN_SMEM>>>(out);
}

// round 15
// speedup vs baseline: 1.0359x; 1.0359x over previous
#include <cuda_runtime.h>
#include <cuda_bf16.h>
#include <cstdint>
#include <cstddef>

#define T_TOK 8192
#define D_DIM 4096
#define I_DIM 11008

// ---------------- device scratch (static, no allocs) ----------------
// Quantized operands stored as INTEGER-VALUED bf16 (exact for |v|<=127).
__device__ __align__(16) __nv_bfloat16 g_Wgb[(size_t)I_DIM * D_DIM];
__device__ __align__(16) __nv_bfloat16 g_Wub[(size_t)I_DIM * D_DIM];
__device__ __align__(16) __nv_bfloat16 g_Wdb[(size_t)D_DIM * I_DIM];
__device__ float g_wsg[I_DIM];
__device__ float g_wsu[I_DIM];
__device__ float g_wsd[D_DIM];
__device__ __align__(16) __nv_bfloat16 g_qb[(size_t)T_TOK * D_DIM];
__device__ float g_s[T_TOK];
__device__ __align__(16) float g_h[(size_t)T_TOK * I_DIM];
__device__ unsigned g_hamax[T_TOK];
__device__ __align__(16) __nv_bfloat16 g_q2b[(size_t)T_TOK * I_DIM];
__device__ float g_s2[T_TOK];

// ---------------- small helpers ----------------
__device__ __forceinline__ float warp_sum(float v) {
#pragma unroll
    for (int o = 16; o; o >>= 1) v += __shfl_xor_sync(0xffffffffu, v, o);
    return v;
}
__device__ __forceinline__ float warp_max(float v) {
#pragma unroll
    for (int o = 16; o; o >>= 1) v = fmaxf(v, __shfl_xor_sync(0xffffffffu, v, o));
    return v;
}
__device__ __forceinline__ float block_sum(float v, float* red) {
    v = warp_sum(v);
    __syncthreads();
    if ((threadIdx.x & 31) == 0) red[threadIdx.x >> 5] = v;
    __syncthreads();
    float r = red[0];
#pragma unroll
    for (int i = 1; i < 8; i++) r += red[i];
    return r;
}
__device__ __forceinline__ float block_max(float v, float* red) {
    v = warp_max(v);
    __syncthreads();
    if ((threadIdx.x & 31) == 0) red[threadIdx.x >> 5] = v;
    __syncthreads();
    float r = red[0];
#pragma unroll
    for (int i = 1; i < 8; i++) r = fmaxf(r, red[i]);
    return r;
}

__device__ __forceinline__ int qint(float x, float s) {
    return max(-127, min(127, __float2int_rn(x / s)));
}
// quantize 2 floats -> packed bf16x2 (integer-valued, exact)
__device__ __forceinline__ uint32_t qpair(float a, float b, float s) {
    __nv_bfloat162 p = __floats2bfloat162_rn((float)qint(a, s), (float)qint(b, s));
    return *(uint32_t*)&p;
}
__device__ __forceinline__ float silu_f(float x) {
    return x / (1.0f + expf(-x));
}

// ---------------- async copy / mma primitives ----------------
__device__ __forceinline__ void cp_async16(uint32_t dst, const void* src) {
    asm volatile("cp.async.cg.shared.global [%0], [%1], 16;\n" :: "r"(dst), "l"(src));
}
__device__ __forceinline__ void cp_commit() { asm volatile("cp.async.commit_group;\n"); }
template <int N> __device__ __forceinline__ void cp_wait() {
    asm volatile("cp.async.wait_group %0;\n" :: "n"(N));
}
__device__ __forceinline__ void ldm_x4(uint32_t addr, uint32_t r[4]) {
    asm volatile("ldmatrix.sync.aligned.m8n8.x4.shared.b16 {%0,%1,%2,%3}, [%4];\n"
                 : "=r"(r[0]), "=r"(r[1]), "=r"(r[2]), "=r"(r[3]) : "r"(addr));
}
__device__ __forceinline__ void mma_bf16(float c[4], const uint32_t a[4],
                                         uint32_t b0, uint32_t b1) {
    asm volatile(
        "mma.sync.aligned.m16n8k16.row.col.f32.bf16.bf16.f32 "
        "{%0,%1,%2,%3}, {%4,%5,%6,%7}, {%8,%9}, {%0,%1,%2,%3};\n"
        : "+f"(c[0]), "+f"(c[1]), "+f"(c[2]), "+f"(c[3])
        : "r"(a[0]), "r"(a[1]), "r"(a[2]), "r"(a[3]), "r"(b0), "r"(b1));
}

// smem tile: rows of 128 bytes (64 bf16); 16B chunk swizzle c' = c ^ (row & 7)
__device__ __forceinline__ uint32_t sw_off(int row, int c) {
    return (uint32_t)(row * 128 + ((c ^ (row & 7)) << 4));
}
// A fragment (16 rows x 16 bf16) via ldmatrix.x4; ks = k16-step within 64-col tile
__device__ __forceinline__ void lda_frag(uint32_t tb, int Rb, int ks, uint32_t a[4]) {
    int L = threadIdx.x & 31;
    int g4 = L >> 3;
    int row = Rb + ((g4 & 1) << 3) + (L & 7);
    int c = 2 * ks + (g4 >> 1);
    ldm_x4(tb + sw_off(row, c), a);
}
// B pair: two 8xk16 n-tiles -> {b0(nt), b1(nt), b0(nt+1), b1(nt+1)}
__device__ __forceinline__ void ldb_pair(uint32_t tb, int Nb, int ks, uint32_t b[4]) {
    int L = threadIdx.x & 31;
    int g4 = L >> 3;
    int row = Nb + ((g4 >> 1) << 3) + (L & 7);
    int c = 2 * ks + (g4 & 1);
    ldm_x4(tb + sw_off(row, c), b);
}

// ---------------- fused front kernel: qw_gate | qw_up | rmsnorm+quant ----------------
// Grid = 2*I_DIM + T_TOK blocks of 256 threads; dispatch on blockIdx.x.
// Three independent HBM-bound passes share full bandwidth in one launch.
__global__ void front_kernel(const float* __restrict__ X, const float* __restrict__ gw,
                             const float* __restrict__ Wg, const float* __restrict__ Wu) {
    __shared__ float red[8];
    const int b = blockIdx.x;
    if (b < 2 * I_DIM) {
        // ---- per-row weight quant for Wg / Wu (row cached in registers) ----
        const bool isg = (b < I_DIM);
        const int row = isg ? b : b - I_DIM;
        const float* W = isg ? Wg : Wu;
        __nv_bfloat16* Wq = isg ? g_Wgb : g_Wub;
        float* ws = isg ? g_wsg : g_wsu;
        const float4* W4 = (const float4*)(W + (size_t)row * D_DIM);
        float4 v[4];
        float amax = 0.0f;
#pragma unroll
        for (int k = 0; k < 4; k++) {
            v[k] = W4[threadIdx.x + k * 256];
            amax = fmaxf(amax, fmaxf(fmaxf(fabsf(v[k].x), fabsf(v[k].y)),
                                     fmaxf(fabsf(v[k].z), fabsf(v[k].w))));
        }
        amax = block_max(amax, red);
        float s = fmaxf(amax / 127.0f, 1e-8f);
        if (threadIdx.x == 0) ws[row] = s;
        uint2* Q2 = (uint2*)(Wq + (size_t)row * D_DIM);
#pragma unroll
        for (int k = 0; k < 4; k++)
            Q2[threadIdx.x + k * 256] = make_uint2(qpair(v[k].x, v[k].y, s),
                                                   qpair(v[k].z, v[k].w, s));
    } else {
        // ---- RMSNorm + per-token activation quant ----
        const int t = b - 2 * I_DIM;
        if (threadIdx.x == 0) g_hamax[t] = 0u;  // reset for gateup epilogue atomics
        const float4* X4 = (const float4*)(X + (size_t)t * D_DIM);
        const float4* W4 = (const float4*)gw;
        float4 xv[4], wv[4];
        float ss = 0.0f;
#pragma unroll
        for (int k = 0; k < 4; k++) {
            int c = threadIdx.x + k * 256;
            xv[k] = X4[c];
            wv[k] = W4[c];
            ss += xv[k].x * xv[k].x + xv[k].y * xv[k].y + xv[k].z * xv[k].z + xv[k].w * xv[k].w;
        }
        ss = block_sum(ss, red);
        float rinv = rsqrtf(ss / (float)D_DIM + 1e-6f);
        float4 vv[4];
        float amax = 0.0f;
#pragma unroll
        for (int k = 0; k < 4; k++) {
            vv[k].x = xv[k].x * rinv * wv[k].x;
            vv[k].y = xv[k].y * rinv * wv[k].y;
            vv[k].z = xv[k].z * rinv * wv[k].z;
            vv[k].w = xv[k].w * rinv * wv[k].w;
            amax = fmaxf(amax, fmaxf(fmaxf(fabsf(vv[k].x), fabsf(vv[k].y)),
                                     fmaxf(fabsf(vv[k].z), fabsf(vv[k].w))));
        }
        amax = block_max(amax, red);
        float s = fmaxf(amax / 127.0f, 1e-8f);
        if (threadIdx.x == 0) g_s[t] = s;
        uint2* Q2 = (uint2*)(g_qb + (size_t)t * D_DIM);
#pragma unroll
        for (int k = 0; k < 4; k++) {
            float4 v = vv[k];
            Q2[threadIdx.x + k * 256] = make_uint2(qpair(v.x, v.y, s), qpair(v.z, v.w, s));
        }
    }
}

// ---------------- Wd weight quant (side stream, overlaps gateup) ----------------
__global__ void quant_wd_kernel(const float* __restrict__ W) {
    __shared__ float red[8];
    const int nch = I_DIM >> 2;  // 2752
    int row = blockIdx.x;
    const float4* W4 = (const float4*)(W + (size_t)row * I_DIM);
    float4 v[11];
    float amax = 0.0f;
#pragma unroll
    for (int k = 0; k < 11; k++) {
        int c = threadIdx.x + k * 256;
        if (c < nch) {
            v[k] = W4[c];
            amax = fmaxf(amax, fmaxf(fmaxf(fabsf(v[k].x), fabsf(v[k].y)),
                                     fmaxf(fabsf(v[k].z), fabsf(v[k].w))));
        }
    }
    amax = block_max(amax, red);
    float s = fmaxf(amax / 127.0f, 1e-8f);
    if (threadIdx.x == 0) g_wsd[row] = s;
    uint2* Q2 = (uint2*)(g_Wdb + (size_t)row * I_DIM);
#pragma unroll
    for (int k = 0; k < 11; k++) {
        int c = threadIdx.x + k * 256;
        if (c < nch)
            Q2[c] = make_uint2(qpair(v[k].x, v[k].y, s), qpair(v[k].z, v[k].w, s));
    }
}

// amax precomputed by gateup epilogue atomics -> single pass over h
__global__ void quant_h_kernel() {
    int t = blockIdx.x;
    float amax = __uint_as_float(g_hamax[t]);
    float s = fmaxf(amax / 127.0f, 1e-8f);
    if (threadIdx.x == 0) g_s2[t] = s;
    const float4* H4 = (const float4*)(g_h + (size_t)t * I_DIM);
    uint2* Q2 = (uint2*)(g_q2b + (size_t)t * I_DIM);
    const int nch = I_DIM >> 2;  // 2752
    for (int c = threadIdx.x; c < nch; c += 256) {
        float4 v = H4[c];
        Q2[c] = make_uint2(qpair(v.x, v.y, s), qpair(v.z, v.w, s));
    }
}

// ---------------- GEMM 1: gate/up fused, SwiGLU epilogue -> g_h ----------------
// Block tile 128x128, K-slab 128 bf16 (two 64-col sub-tiles), 8 warps (4m x 2n),
// warp tile 32x64 for BOTH gate and up, 2 stages x 96KB, 256 threads.
// Sub-tile layout within a stage: [A0 16K][A1 16K][Bg0][Bg1][Bu0][Bu1].
#define GU_SUB   16384
#define GU_STAGE (6 * GU_SUB)   // 96 KB
#define GU_NSTG  2
#define GU_SMEM  (GU_NSTG * GU_STAGE)

__global__ __launch_bounds__(256, 1) void gemm_gateup_kernel() {
    extern __shared__ __align__(128) int8_t sm[];
    const int tid = threadIdx.x;
    const int lane = tid & 31;
    const int wid = tid >> 5;
    const int wm = wid >> 1;  // 0..3
    const int wn = wid & 1;   // 0..1
    const int by = blockIdx.x;  // T tile (64) fast -> weight L2 reuse
    const int bx = blockIdx.y;  // I tile (86)
    const uint32_t smbase = (uint32_t)__cvta_generic_to_shared(sm);

    float accg[2][8][4];
    float accu[2][8][4];
#pragma unroll
    for (int a = 0; a < 2; a++)
#pragma unroll
        for (int b = 0; b < 8; b++)
#pragma unroll
            for (int c = 0; c < 4; c++) { accg[a][b][c] = 0.0f; accu[a][b][c] = 0.0f; }

    // One K-slab = 128 bf16 = two 64-col sub-tiles per operand.
    auto load_stage = [&](int stage, int kt) {
        const size_t k0 = (size_t)kt * 128;
#pragma unroll
        for (int j = 0; j < 24; j++) {
            int cid = tid + j * 256;      // 0..6143
            int sub = cid >> 10;          // 0..5: A0 A1 Bg0 Bg1 Bu0 Bu1
            int q = cid & 1023;
            int row = q >> 3, c = q & 7;
            uint32_t dst = smbase + stage * GU_STAGE + sub * GU_SUB + sw_off(row, c);
            int khalf = (sub & 1) * 64;
            const __nv_bfloat16* src;
            if (sub < 2)      src = g_qb  + (size_t)(by * 128 + row) * D_DIM + k0 + khalf + c * 8;
            else if (sub < 4) src = g_Wgb + (size_t)(bx * 128 + row) * D_DIM + k0 + khalf + c * 8;
            else              src = g_Wub + (size_t)(bx * 128 + row) * D_DIM + k0 + khalf + c * 8;
            cp_async16(dst, src);
        }
    };

    load_stage(0, 0); cp_commit();

    const int KT = D_DIM / 128;  // 32
    for (int kt = 0; kt < KT; kt++) {
        cp_wait<0>();
        __syncthreads();
        if (kt + 1 < KT) { load_stage((kt + 1) & 1, kt + 1); cp_commit(); }

        uint32_t st = smbase + (kt & 1) * GU_STAGE;
#pragma unroll
        for (int kss = 0; kss < 8; kss++) {       // 8 k16-steps per slab
            int half = kss >> 2;                  // sub-tile index
            int ks = kss & 3;                     // k16 within sub-tile
            uint32_t ta  = st + half * GU_SUB;
            uint32_t tbg = st + (2 + half) * GU_SUB;
            uint32_t tbu = st + (4 + half) * GU_SUB;
            uint32_t a[2][4];
            lda_frag(ta, wm * 32,      ks, a[0]);
            lda_frag(ta, wm * 32 + 16, ks, a[1]);
#pragma unroll
            for (int j = 0; j < 4; j++) {
                uint32_t bg[4], bu[4];
                ldb_pair(tbg, wn * 64 + j * 16, ks, bg);
                ldb_pair(tbu, wn * 64 + j * 16, ks, bu);
#pragma unroll
                for (int mt = 0; mt < 2; mt++) {
                    mma_bf16(accg[mt][2 * j],     a[mt], bg[0], bg[1]);
                    mma_bf16(accg[mt][2 * j + 1], a[mt], bg[2], bg[3]);
                    mma_bf16(accu[mt][2 * j],     a[mt], bu[0], bu[1]);
                    mma_bf16(accu[mt][2 * j + 1], a[mt], bu[2], bu[3]);
                }
            }
        }
    }

    // epilogue: dequant, SwiGLU, store h (fp32), per-token amax atomic
    const int g = lane >> 2, tg = lane & 3;
#pragma unroll
    for (int mt = 0; mt < 2; mt++) {
        int t0 = by * 128 + wm * 32 + mt * 16 + g;
        float s0 = g_s[t0];
        float s1 = g_s[t0 + 8];
        float m0 = 0.0f, m1 = 0.0f;
#pragma unroll
        for (int nt = 0; nt < 8; nt++) {
            int i0 = bx * 128 + wn * 64 + nt * 8 + tg * 2;
            float wg0 = g_wsg[i0], wg1 = g_wsg[i0 + 1];
            float wu0 = g_wsu[i0], wu1 = g_wsu[i0 + 1];
            float ga = accg[mt][nt][0] * s0 * wg0;
            float gb = accg[mt][nt][1] * s0 * wg1;
            float gc = accg[mt][nt][2] * s1 * wg0;
            float gd = accg[mt][nt][3] * s1 * wg1;
            float ua = accu[mt][nt][0] * s0 * wu0;
            float ub = accu[mt][nt][1] * s0 * wu1;
            float uc = accu[mt][nt][2] * s1 * wu0;
            float ud = accu[mt][nt][3] * s1 * wu1;
            float2 r0 = make_float2(silu_f(ga) * ua, silu_f(gb) * ub);
            float2 r1 = make_float2(silu_f(gc) * uc, silu_f(gd) * ud);
            m0 = fmaxf(m0, fmaxf(fabsf(r0.x), fabsf(r0.y)));
            m1 = fmaxf(m1, fmaxf(fabsf(r1.x), fabsf(r1.y)));
            *(float2*)(g_h + (size_t)t0 * I_DIM + i0)       = r0;
            *(float2*)(g_h + (size_t)(t0 + 8) * I_DIM + i0) = r1;
        }
        m0 = fmaxf(m0, __shfl_xor_sync(0xffffffffu, m0, 1));
        m0 = fmaxf(m0, __shfl_xor_sync(0xffffffffu, m0, 2));
        m1 = fmaxf(m1, __shfl_xor_sync(0xffffffffu, m1, 1));
        m1 = fmaxf(m1, __shfl_xor_sync(0xffffffffu, m1, 2));
        if (tg == 0) {
            atomicMax(&g_hamax[t0],     __float_as_uint(m0));
            atomicMax(&g_hamax[t0 + 8], __float_as_uint(m1));
        }
    }
}

// ---------------- GEMM 2: down proj -> d_out ----------------
// Block 128x128, 8 warps 4m x 2n, warp tile 32x64, 3 stages, 2 CTAs/SM.
#define DN_STAGE 32768  // A 16K + B 16K
#define DN_NSTG 3
#define DN_SMEM (DN_NSTG * DN_STAGE)

__global__ __launch_bounds__(256, 2) void gemm_down_kernel(float* __restrict__ out) {
    extern __shared__ __align__(128) int8_t sm[];
    const int tid = threadIdx.x;
    const int lane = tid & 31;
    const int wid = tid >> 5;
    const int wm = wid >> 1;
    const int wn = wid & 1;
    const int by = blockIdx.x;  // T tile (64)
    const int bx = blockIdx.y;  // D tile (32)
    const uint32_t smbase = (uint32_t)__cvta_generic_to_shared(sm);

    float acc[2][8][4];
#pragma unroll
    for (int a = 0; a < 2; a++)
#pragma unroll
        for (int b = 0; b < 8; b++)
#pragma unroll
            for (int c = 0; c < 4; c++) acc[a][b][c] = 0.0f;

    auto load_stage = [&](int stage, int kt) {
        const size_t k0 = (size_t)kt * 64;
#pragma unroll
        for (int j = 0; j < 8; j++) {
            int cid = tid + j * 256;      // 0..2047
            int region = cid >> 10;       // 0:A 1:B
            int q = cid & 1023;
            int row = q >> 3, c = q & 7;
            uint32_t dst = smbase + stage * DN_STAGE + region * 16384 + sw_off(row, c);
            const __nv_bfloat16* src;
            if (region == 0) src = g_q2b + (size_t)(by * 128 + row) * I_DIM + k0 + c * 8;
            else             src = g_Wdb + (size_t)(bx * 128 + row) * I_DIM + k0 + c * 8;
            cp_async16(dst, src);
        }
    };

    load_stage(0, 0); cp_commit();
    load_stage(1, 1); cp_commit();

    const int KT = I_DIM / 64;  // 172
    for (int kt = 0; kt < KT; kt++) {
        cp_wait<DN_NSTG - 2>();
        __syncthreads();
        int nxt = kt + DN_NSTG - 1;
        if (nxt < KT) load_stage(nxt % DN_NSTG, nxt);
        cp_commit();

        uint32_t tb = smbase + (kt % DN_NSTG) * DN_STAGE;
        uint32_t tbb = tb + 16384;
#pragma unroll
        for (int ks = 0; ks < 4; ks++) {
            uint32_t a[2][4];
            lda_frag(tb, wm * 32,      ks, a[0]);
            lda_frag(tb, wm * 32 + 16, ks, a[1]);
#pragma unroll
            for (int j = 0; j < 4; j++) {
                uint32_t bb[4];
                ldb_pair(tbb, wn * 64 + j * 16, ks, bb);
#pragma unroll
                for (int mt = 0; mt < 2; mt++) {
                    mma_bf16(acc[mt][2 * j],     a[mt], bb[0], bb[1]);
                    mma_bf16(acc[mt][2 * j + 1], a[mt], bb[2], bb[3]);
                }
            }
        }
    }

    const int g = lane >> 2, tg = lane & 3;
#pragma unroll
    for (int mt = 0; mt < 2; mt++) {
        int t0 = by * 128 + wm * 32 + mt * 16 + g;
        float s0 = g_s2[t0];
        float s1 = g_s2[t0 + 8];
#pragma unroll
        for (int nt = 0; nt < 8; nt++) {
            int d0 = bx * 128 + wn * 64 + nt * 8 + tg * 2;
            float w0 = g_wsd[d0], w1 = g_wsd[d0 + 1];
            float2 r0 = make_float2(acc[mt][nt][0] * s0 * w0,
                                    acc[mt][nt][1] * s0 * w1);
            float2 r1 = make_float2(acc[mt][nt][2] * s1 * w0,
                                    acc[mt][nt][3] * s1 * w1);
            *(float2*)(out + (size_t)t0 * D_DIM + d0)       = r0;
            *(float2*)(out + (size_t)(t0 + 8) * D_DIM + d0) = r1;
        }
    }
}

// ---------------- launch ----------------
extern "C" void kernel_launch(void* const* d_in, const int* in_sizes, int n_in,
                              void* d_out, int out_size) {
    const float* X  = (const float*)d_in[0];  // hidden_states [4,2048,4096]
    const float* gw = (const float*)d_in[1];  // rmsnorm_weight [4096]
    const float* Wg = (const float*)d_in[2];  // [11008,4096]
    const float* Wu = (const float*)d_in[3];  // [11008,4096]
    const float* Wd = (const float*)d_in[4];  // [4096,11008]
    float* out = (float*)d_out;

    static cudaStream_t s2 = nullptr;
    static cudaEvent_t evF = nullptr, evD = nullptr;
    if (s2 == nullptr) {
        cudaFuncSetAttribute(gemm_gateup_kernel, cudaFuncAttributeMaxDynamicSharedMemorySize, GU_SMEM);
        cudaFuncSetAttribute(gemm_down_kernel,   cudaFuncAttributeMaxDynamicSharedMemorySize, DN_SMEM);
        cudaStreamCreateWithFlags(&s2, cudaStreamNonBlocking);
        cudaEventCreateWithFlags(&evF, cudaEventDisableTiming);
        cudaEventCreateWithFlags(&evD, cudaEventDisableTiming);
    }

    // Fused front (main stream): qw_gate | qw_up | rmsnorm+quant in one launch.
    front_kernel<<<2 * I_DIM + T_TOK, 256>>>(X, gw, Wg, Wu);

    // Fork: Wd quantization on side stream, concurrent with gateup GEMM.
    cudaEventRecord(evF, 0);
    cudaStreamWaitEvent(s2, evF, 0);
    quant_wd_kernel<<<D_DIM, 256, 0, s2>>>(Wd);
    cudaEventRecord(evD, s2);

    // Gateup GEMM (proven R8 config) + quant_h on main stream.
    gemm_gateup_kernel<<<dim3(T_TOK / 128, I_DIM / 128), 256, GU_SMEM>>>();
    quant_h_kernel<<<T_TOK, 256>>>();

    // Join: down GEMM needs both q2 (main) and quantized Wd (side stream).
    cudaStreamWaitEvent(0, evD, 0);
    gemm_down_kernel<<<dim3(T_TOK / 128, D_DIM / 128), 256, DN_SMEM>>>(out);
}

// round 16
// speedup vs baseline: 1.0375x; 1.0015x over previous
#include <cuda_runtime.h>
#include <cuda_bf16.h>
#include <cstdint>
#include <cstddef>

#define T_TOK 8192
#define D_DIM 4096
#define I_DIM 11008

// ---------------- device scratch (static, no allocs) ----------------
// Quantized operands stored as INTEGER-VALUED bf16 (exact for |v|<=127).
__device__ __align__(16) __nv_bfloat16 g_Wgb[(size_t)I_DIM * D_DIM];
__device__ __align__(16) __nv_bfloat16 g_Wub[(size_t)I_DIM * D_DIM];
__device__ __align__(16) __nv_bfloat16 g_Wdb[(size_t)D_DIM * I_DIM];
__device__ float g_wsg[I_DIM];
__device__ float g_wsu[I_DIM];
__device__ float g_wsd[D_DIM];
__device__ __align__(16) __nv_bfloat16 g_qb[(size_t)T_TOK * D_DIM];
__device__ float g_s[T_TOK];
__device__ __align__(16) float g_h[(size_t)T_TOK * I_DIM];
__device__ unsigned g_hamax[T_TOK];
__device__ __align__(16) __nv_bfloat16 g_q2b[(size_t)T_TOK * I_DIM];
__device__ float g_s2[T_TOK];

// ---------------- small helpers ----------------
__device__ __forceinline__ float warp_sum(float v) {
#pragma unroll
    for (int o = 16; o; o >>= 1) v += __shfl_xor_sync(0xffffffffu, v, o);
    return v;
}
__device__ __forceinline__ float warp_max(float v) {
#pragma unroll
    for (int o = 16; o; o >>= 1) v = fmaxf(v, __shfl_xor_sync(0xffffffffu, v, o));
    return v;
}
__device__ __forceinline__ float block_sum(float v, float* red) {
    v = warp_sum(v);
    __syncthreads();
    if ((threadIdx.x & 31) == 0) red[threadIdx.x >> 5] = v;
    __syncthreads();
    float r = red[0];
#pragma unroll
    for (int i = 1; i < 8; i++) r += red[i];
    return r;
}
__device__ __forceinline__ float block_max(float v, float* red) {
    v = warp_max(v);
    __syncthreads();
    if ((threadIdx.x & 31) == 0) red[threadIdx.x >> 5] = v;
    __syncthreads();
    float r = red[0];
#pragma unroll
    for (int i = 1; i < 8; i++) r = fmaxf(r, red[i]);
    return r;
}

__device__ __forceinline__ int qint(float x, float s) {
    return max(-127, min(127, __float2int_rn(x / s)));
}
// quantize 2 floats -> packed bf16x2 (integer-valued, exact)
__device__ __forceinline__ uint32_t qpair(float a, float b, float s) {
    __nv_bfloat162 p = __floats2bfloat162_rn((float)qint(a, s), (float)qint(b, s));
    return *(uint32_t*)&p;
}
__device__ __forceinline__ float silu_f(float x) {
    return x / (1.0f + expf(-x));
}

// ---------------- async copy / mma primitives ----------------
__device__ __forceinline__ void cp_async16(uint32_t dst, const void* src) {
    asm volatile("cp.async.cg.shared.global [%0], [%1], 16;\n" :: "r"(dst), "l"(src));
}
__device__ __forceinline__ void cp_commit() { asm volatile("cp.async.commit_group;\n"); }
template <int N> __device__ __forceinline__ void cp_wait() {
    asm volatile("cp.async.wait_group %0;\n" :: "n"(N));
}
__device__ __forceinline__ void ldm_x4(uint32_t addr, uint32_t r[4]) {
    asm volatile("ldmatrix.sync.aligned.m8n8.x4.shared.b16 {%0,%1,%2,%3}, [%4];\n"
                 : "=r"(r[0]), "=r"(r[1]), "=r"(r[2]), "=r"(r[3]) : "r"(addr));
}
__device__ __forceinline__ void mma_bf16(float c[4], const uint32_t a[4],
                                         uint32_t b0, uint32_t b1) {
    asm volatile(
        "mma.sync.aligned.m16n8k16.row.col.f32.bf16.bf16.f32 "
        "{%0,%1,%2,%3}, {%4,%5,%6,%7}, {%8,%9}, {%0,%1,%2,%3};\n"
        : "+f"(c[0]), "+f"(c[1]), "+f"(c[2]), "+f"(c[3])
        : "r"(a[0]), "r"(a[1]), "r"(a[2]), "r"(a[3]), "r"(b0), "r"(b1));
}

// smem tile: rows of 128 bytes (64 bf16); 16B chunk swizzle c' = c ^ (row & 7)
__device__ __forceinline__ uint32_t sw_off(int row, int c) {
    return (uint32_t)(row * 128 + ((c ^ (row & 7)) << 4));
}
// A fragment (16 rows x 16 bf16) via ldmatrix.x4; ks = k16-step within 64-col tile
__device__ __forceinline__ void lda_frag(uint32_t tb, int Rb, int ks, uint32_t a[4]) {
    int L = threadIdx.x & 31;
    int g4 = L >> 3;
    int row = Rb + ((g4 & 1) << 3) + (L & 7);
    int c = 2 * ks + (g4 >> 1);
    ldm_x4(tb + sw_off(row, c), a);
}
// B pair: two 8xk16 n-tiles -> {b0(nt), b1(nt), b0(nt+1), b1(nt+1)}
__device__ __forceinline__ void ldb_pair(uint32_t tb, int Nb, int ks, uint32_t b[4]) {
    int L = threadIdx.x & 31;
    int g4 = L >> 3;
    int row = Nb + ((g4 >> 1) << 3) + (L & 7);
    int c = 2 * ks + (g4 & 1);
    ldm_x4(tb + sw_off(row, c), b);
}

// ---------------- fused front kernel: qw_gate | qw_up | rmsnorm+quant ----------------
// Grid = 2*I_DIM + T_TOK blocks of 256 threads; dispatch on blockIdx.x.
__global__ void front_kernel(const float* __restrict__ X, const float* __restrict__ gw,
                             const float* __restrict__ Wg, const float* __restrict__ Wu) {
    __shared__ float red[8];
    const int b = blockIdx.x;
    if (b < 2 * I_DIM) {
        // ---- per-row weight quant for Wg / Wu (row cached in registers) ----
        const bool isg = (b < I_DIM);
        const int row = isg ? b : b - I_DIM;
        const float* W = isg ? Wg : Wu;
        __nv_bfloat16* Wq = isg ? g_Wgb : g_Wub;
        float* ws = isg ? g_wsg : g_wsu;
        const float4* W4 = (const float4*)(W + (size_t)row * D_DIM);
        float4 v[4];
        float amax = 0.0f;
#pragma unroll
        for (int k = 0; k < 4; k++) {
            v[k] = W4[threadIdx.x + k * 256];
            amax = fmaxf(amax, fmaxf(fmaxf(fabsf(v[k].x), fabsf(v[k].y)),
                                     fmaxf(fabsf(v[k].z), fabsf(v[k].w))));
        }
        amax = block_max(amax, red);
        float s = fmaxf(amax / 127.0f, 1e-8f);
        if (threadIdx.x == 0) ws[row] = s;
        uint2* Q2 = (uint2*)(Wq + (size_t)row * D_DIM);
#pragma unroll
        for (int k = 0; k < 4; k++)
            Q2[threadIdx.x + k * 256] = make_uint2(qpair(v[k].x, v[k].y, s),
                                                   qpair(v[k].z, v[k].w, s));
    } else {
        // ---- RMSNorm + per-token activation quant ----
        const int t = b - 2 * I_DIM;
        if (threadIdx.x == 0) g_hamax[t] = 0u;  // reset for gateup epilogue atomics
        const float4* X4 = (const float4*)(X + (size_t)t * D_DIM);
        const float4* W4 = (const float4*)gw;
        float4 xv[4], wv[4];
        float ss = 0.0f;
#pragma unroll
        for (int k = 0; k < 4; k++) {
            int c = threadIdx.x + k * 256;
            xv[k] = X4[c];
            wv[k] = W4[c];
            ss += xv[k].x * xv[k].x + xv[k].y * xv[k].y + xv[k].z * xv[k].z + xv[k].w * xv[k].w;
        }
        ss = block_sum(ss, red);
        float rinv = rsqrtf(ss / (float)D_DIM + 1e-6f);
        float4 vv[4];
        float amax = 0.0f;
#pragma unroll
        for (int k = 0; k < 4; k++) {
            vv[k].x = xv[k].x * rinv * wv[k].x;
            vv[k].y = xv[k].y * rinv * wv[k].y;
            vv[k].z = xv[k].z * rinv * wv[k].z;
            vv[k].w = xv[k].w * rinv * wv[k].w;
            amax = fmaxf(amax, fmaxf(fmaxf(fabsf(vv[k].x), fabsf(vv[k].y)),
                                     fmaxf(fabsf(vv[k].z), fabsf(vv[k].w))));
        }
        amax = block_max(amax, red);
        float s = fmaxf(amax / 127.0f, 1e-8f);
        if (threadIdx.x == 0) g_s[t] = s;
        uint2* Q2 = (uint2*)(g_qb + (size_t)t * D_DIM);
#pragma unroll
        for (int k = 0; k < 4; k++) {
            float4 v = vv[k];
            Q2[threadIdx.x + k * 256] = make_uint2(qpair(v.x, v.y, s), qpair(v.z, v.w, s));
        }
    }
}

// ---------------- Wd weight quant (side stream, overlaps gateup) ----------------
__global__ void quant_wd_kernel(const float* __restrict__ W) {
    __shared__ float red[8];
    const int nch = I_DIM >> 2;  // 2752
    int row = blockIdx.x;
    const float4* W4 = (const float4*)(W + (size_t)row * I_DIM);
    float4 v[11];
    float amax = 0.0f;
#pragma unroll
    for (int k = 0; k < 11; k++) {
        int c = threadIdx.x + k * 256;
        if (c < nch) {
            v[k] = W4[c];
            amax = fmaxf(amax, fmaxf(fmaxf(fabsf(v[k].x), fabsf(v[k].y)),
                                     fmaxf(fabsf(v[k].z), fabsf(v[k].w))));
        }
    }
    amax = block_max(amax, red);
    float s = fmaxf(amax / 127.0f, 1e-8f);
    if (threadIdx.x == 0) g_wsd[row] = s;
    uint2* Q2 = (uint2*)(g_Wdb + (size_t)row * I_DIM);
#pragma unroll
    for (int k = 0; k < 11; k++) {
        int c = threadIdx.x + k * 256;
        if (c < nch)
            Q2[c] = make_uint2(qpair(v[k].x, v[k].y, s), qpair(v[k].z, v[k].w, s));
    }
}

// ---------------- quant_h: 2 blocks per token, register-batched loads ----------
// Grid = 2*T_TOK. Block b handles token b>>1, half b&1 (1376 of 2752 chunks).
// amax precomputed by gateup epilogue atomics -> single pass over h.
#define QH_HALF 1376   // chunks per half-row
#define QH_PER  6      // ceil(1376 / 256)

__global__ void quant_h_kernel() {
    const int t = blockIdx.x >> 1;
    const int half = blockIdx.x & 1;
    float amax = __uint_as_float(g_hamax[t]);
    float s = fmaxf(amax / 127.0f, 1e-8f);
    if (half == 0 && threadIdx.x == 0) g_s2[t] = s;
    const float4* H4 = (const float4*)(g_h + (size_t)t * I_DIM) + half * QH_HALF;
    uint2* Q2 = (uint2*)(g_q2b + (size_t)t * I_DIM) + half * QH_HALF;
    // register-batch the independent loads (high MLP), then convert+store
    float4 v[QH_PER];
#pragma unroll
    for (int k = 0; k < QH_PER; k++) {
        int c = threadIdx.x + k * 256;
        if (c < QH_HALF) v[k] = H4[c];
    }
#pragma unroll
    for (int k = 0; k < QH_PER; k++) {
        int c = threadIdx.x + k * 256;
        if (c < QH_HALF)
            Q2[c] = make_uint2(qpair(v[k].x, v[k].y, s), qpair(v[k].z, v[k].w, s));
    }
}

// ---------------- GEMM 1: gate/up fused, SwiGLU epilogue -> g_h ----------------
// Block tile 128x128, K-slab 128 bf16 (two 64-col sub-tiles), 8 warps (4m x 2n),
// warp tile 32x64 for BOTH gate and up, 2 stages x 96KB, 256 threads.
// Sub-tile layout within a stage: [A0 16K][A1 16K][Bg0][Bg1][Bu0][Bu1].
#define GU_SUB   16384
#define GU_STAGE (6 * GU_SUB)   // 96 KB
#define GU_NSTG  2
#define GU_SMEM  (GU_NSTG * GU_STAGE)

__global__ __launch_bounds__(256, 1) void gemm_gateup_kernel() {
    extern __shared__ __align__(128) int8_t sm[];
    const int tid = threadIdx.x;
    const int lane = tid & 31;
    const int wid = tid >> 5;
    const int wm = wid >> 1;  // 0..3
    const int wn = wid & 1;   // 0..1
    const int by = blockIdx.x;  // T tile (64) fast -> weight L2 reuse
    const int bx = blockIdx.y;  // I tile (86)
    const uint32_t smbase = (uint32_t)__cvta_generic_to_shared(sm);

    float accg[2][8][4];
    float accu[2][8][4];
#pragma unroll
    for (int a = 0; a < 2; a++)
#pragma unroll
        for (int b = 0; b < 8; b++)
#pragma unroll
            for (int c = 0; c < 4; c++) { accg[a][b][c] = 0.0f; accu[a][b][c] = 0.0f; }

    // One K-slab = 128 bf16 = two 64-col sub-tiles per operand.
    auto load_stage = [&](int stage, int kt) {
        const size_t k0 = (size_t)kt * 128;
#pragma unroll
        for (int j = 0; j < 24; j++) {
            int cid = tid + j * 256;      // 0..6143
            int sub = cid >> 10;          // 0..5: A0 A1 Bg0 Bg1 Bu0 Bu1
            int q = cid & 1023;
            int row = q >> 3, c = q & 7;
            uint32_t dst = smbase + stage * GU_STAGE + sub * GU_SUB + sw_off(row, c);
            int khalf = (sub & 1) * 64;
            const __nv_bfloat16* src;
            if (sub < 2)      src = g_qb  + (size_t)(by * 128 + row) * D_DIM + k0 + khalf + c * 8;
            else if (sub < 4) src = g_Wgb + (size_t)(bx * 128 + row) * D_DIM + k0 + khalf + c * 8;
            else              src = g_Wub + (size_t)(bx * 128 + row) * D_DIM + k0 + khalf + c * 8;
            cp_async16(dst, src);
        }
    };

    load_stage(0, 0); cp_commit();

    const int KT = D_DIM / 128;  // 32
    for (int kt = 0; kt < KT; kt++) {
        cp_wait<0>();
        __syncthreads();
        if (kt + 1 < KT) { load_stage((kt + 1) & 1, kt + 1); cp_commit(); }

        uint32_t st = smbase + (kt & 1) * GU_STAGE;
#pragma unroll
        for (int kss = 0; kss < 8; kss++) {       // 8 k16-steps per slab
            int half = kss >> 2;                  // sub-tile index
            int ks = kss & 3;                     // k16 within sub-tile
            uint32_t ta  = st + half * GU_SUB;
            uint32_t tbg = st + (2 + half) * GU_SUB;
            uint32_t tbu = st + (4 + half) * GU_SUB;
            uint32_t a[2][4];
            lda_frag(ta, wm * 32,      ks, a[0]);
            lda_frag(ta, wm * 32 + 16, ks, a[1]);
#pragma unroll
            for (int j = 0; j < 4; j++) {
                uint32_t bg[4], bu[4];
                ldb_pair(tbg, wn * 64 + j * 16, ks, bg);
                ldb_pair(tbu, wn * 64 + j * 16, ks, bu);
#pragma unroll
                for (int mt = 0; mt < 2; mt++) {
                    mma_bf16(accg[mt][2 * j],     a[mt], bg[0], bg[1]);
                    mma_bf16(accg[mt][2 * j + 1], a[mt], bg[2], bg[3]);
                    mma_bf16(accu[mt][2 * j],     a[mt], bu[0], bu[1]);
                    mma_bf16(accu[mt][2 * j + 1], a[mt], bu[2], bu[3]);
                }
            }
        }
    }

    // epilogue: dequant, SwiGLU, store h (fp32), per-token amax atomic
    const int g = lane >> 2, tg = lane & 3;
#pragma unroll
    for (int mt = 0; mt < 2; mt++) {
        int t0 = by * 128 + wm * 32 + mt * 16 + g;
        float s0 = g_s[t0];
        float s1 = g_s[t0 + 8];
        float m0 = 0.0f, m1 = 0.0f;
#pragma unroll
        for (int nt = 0; nt < 8; nt++) {
            int i0 = bx * 128 + wn * 64 + nt * 8 + tg * 2;
            float wg0 = g_wsg[i0], wg1 = g_wsg[i0 + 1];
            float wu0 = g_wsu[i0], wu1 = g_wsu[i0 + 1];
            float ga = accg[mt][nt][0] * s0 * wg0;
            float gb = accg[mt][nt][1] * s0 * wg1;
            float gc = accg[mt][nt][2] * s1 * wg0;
            float gd = accg[mt][nt][3] * s1 * wg1;
            float ua = accu[mt][nt][0] * s0 * wu0;
            float ub = accu[mt][nt][1] * s0 * wu1;
            float uc = accu[mt][nt][2] * s1 * wu0;
            float ud = accu[mt][nt][3] * s1 * wu1;
            float2 r0 = make_float2(silu_f(ga) * ua, silu_f(gb) * ub);
            float2 r1 = make_float2(silu_f(gc) * uc, silu_f(gd) * ud);
            m0 = fmaxf(m0, fmaxf(fabsf(r0.x), fabsf(r0.y)));
            m1 = fmaxf(m1, fmaxf(fabsf(r1.x), fabsf(r1.y)));
            *(float2*)(g_h + (size_t)t0 * I_DIM + i0)       = r0;
            *(float2*)(g_h + (size_t)(t0 + 8) * I_DIM + i0) = r1;
        }
        m0 = fmaxf(m0, __shfl_xor_sync(0xffffffffu, m0, 1));
        m0 = fmaxf(m0, __shfl_xor_sync(0xffffffffu, m0, 2));
        m1 = fmaxf(m1, __shfl_xor_sync(0xffffffffu, m1, 1));
        m1 = fmaxf(m1, __shfl_xor_sync(0xffffffffu, m1, 2));
        if (tg == 0) {
            atomicMax(&g_hamax[t0],     __float_as_uint(m0));
            atomicMax(&g_hamax[t0 + 8], __float_as_uint(m1));
        }
    }
}

// ---------------- GEMM 2: down proj -> d_out ----------------
// Block 128x128, 8 warps 4m x 2n, warp tile 32x64, 3 stages, 2 CTAs/SM.
#define DN_STAGE 32768  // A 16K + B 16K
#define DN_NSTG 3
#define DN_SMEM (DN_NSTG * DN_STAGE)

__global__ __launch_bounds__(256, 2) void gemm_down_kernel(float* __restrict__ out) {
    extern __shared__ __align__(128) int8_t sm[];
    const int tid = threadIdx.x;
    const int lane = tid & 31;
    const int wid = tid >> 5;
    const int wm = wid >> 1;
    const int wn = wid & 1;
    const int by = blockIdx.x;  // T tile (64)
    const int bx = blockIdx.y;  // D tile (32)
    const uint32_t smbase = (uint32_t)__cvta_generic_to_shared(sm);

    float acc[2][8][4];
#pragma unroll
    for (int a = 0; a < 2; a++)
#pragma unroll
        for (int b = 0; b < 8; b++)
#pragma unroll
            for (int c = 0; c < 4; c++) acc[a][b][c] = 0.0f;

    auto load_stage = [&](int stage, int kt) {
        const size_t k0 = (size_t)kt * 64;
#pragma unroll
        for (int j = 0; j < 8; j++) {
            int cid = tid + j * 256;      // 0..2047
            int region = cid >> 10;       // 0:A 1:B
            int q = cid & 1023;
            int row = q >> 3, c = q & 7;
            uint32_t dst = smbase + stage * DN_STAGE + region * 16384 + sw_off(row, c);
            const __nv_bfloat16* src;
            if (region == 0) src = g_q2b + (size_t)(by * 128 + row) * I_DIM + k0 + c * 8;
            else             src = g_Wdb + (size_t)(bx * 128 + row) * I_DIM + k0 + c * 8;
            cp_async16(dst, src);
        }
    };

    load_stage(0, 0); cp_commit();
    load_stage(1, 1); cp_commit();

    const int KT = I_DIM / 64;  // 172
    for (int kt = 0; kt < KT; kt++) {
        cp_wait<DN_NSTG - 2>();
        __syncthreads();
        int nxt = kt + DN_NSTG - 1;
        if (nxt < KT) load_stage(nxt % DN_NSTG, nxt);
        cp_commit();

        uint32_t tb = smbase + (kt % DN_NSTG) * DN_STAGE;
        uint32_t tbb = tb + 16384;
#pragma unroll
        for (int ks = 0; ks < 4; ks++) {
            uint32_t a[2][4];
            lda_frag(tb, wm * 32,      ks, a[0]);
            lda_frag(tb, wm * 32 + 16, ks, a[1]);
#pragma unroll
            for (int j = 0; j < 4; j++) {
                uint32_t bb[4];
                ldb_pair(tbb, wn * 64 + j * 16, ks, bb);
#pragma unroll
                for (int mt = 0; mt < 2; mt++) {
                    mma_bf16(acc[mt][2 * j],     a[mt], bb[0], bb[1]);
                    mma_bf16(acc[mt][2 * j + 1], a[mt], bb[2], bb[3]);
                }
            }
        }
    }

    const int g = lane >> 2, tg = lane & 3;
#pragma unroll
    for (int mt = 0; mt < 2; mt++) {
        int t0 = by * 128 + wm * 32 + mt * 16 + g;
        float s0 = g_s2[t0];
        float s1 = g_s2[t0 + 8];
#pragma unroll
        for (int nt = 0; nt < 8; nt++) {
            int d0 = bx * 128 + wn * 64 + nt * 8 + tg * 2;
            float w0 = g_wsd[d0], w1 = g_wsd[d0 + 1];
            float2 r0 = make_float2(acc[mt][nt][0] * s0 * w0,
                                    acc[mt][nt][1] * s0 * w1);
            float2 r1 = make_float2(acc[mt][nt][2] * s1 * w0,
                                    acc[mt][nt][3] * s1 * w1);
            *(float2*)(out + (size_t)t0 * D_DIM + d0)       = r0;
            *(float2*)(out + (size_t)(t0 + 8) * D_DIM + d0) = r1;
        }
    }
}

// ---------------- launch ----------------
extern "C" void kernel_launch(void* const* d_in, const int* in_sizes, int n_in,
                              void* d_out, int out_size) {
    const float* X  = (const float*)d_in[0];  // hidden_states [4,2048,4096]
    const float* gw = (const float*)d_in[1];  // rmsnorm_weight [4096]
    const float* Wg = (const float*)d_in[2];  // [11008,4096]
    const float* Wu = (const float*)d_in[3];  // [11008,4096]
    const float* Wd = (const float*)d_in[4];  // [4096,11008]
    float* out = (float*)d_out;

    static cudaStream_t s2 = nullptr;
    static cudaEvent_t evF = nullptr, evD = nullptr;
    if (s2 == nullptr) {
        cudaFuncSetAttribute(gemm_gateup_kernel, cudaFuncAttributeMaxDynamicSharedMemorySize, GU_SMEM);
        cudaFuncSetAttribute(gemm_down_kernel,   cudaFuncAttributeMaxDynamicSharedMemorySize, DN_SMEM);
        cudaStreamCreateWithFlags(&s2, cudaStreamNonBlocking);
        cudaEventCreateWithFlags(&evF, cudaEventDisableTiming);
        cudaEventCreateWithFlags(&evD, cudaEventDisableTiming);
    }

    // Fused front (main stream): qw_gate | qw_up | rmsnorm+quant in one launch.
    front_kernel<<<2 * I_DIM + T_TOK, 256>>>(X, gw, Wg, Wu);

    // Fork: Wd quantization on side stream, concurrent with gateup GEMM.
    cudaEventRecord(evF, 0);
    cudaStreamWaitEvent(s2, evF, 0);
    quant_wd_kernel<<<D_DIM, 256, 0, s2>>>(Wd);
    cudaEventRecord(evD, s2);

    // Gateup GEMM (proven R8 config) + quant_h on main stream.
    gemm_gateup_kernel<<<dim3(T_TOK / 128, I_DIM / 128), 256, GU_SMEM>>>();
    quant_h_kernel<<<2 * T_TOK, 256>>>();

    // Join: down GEMM needs both q2 (main) and quantized Wd (side stream).
    cudaStreamWaitEvent(0, evD, 0);
    gemm_down_kernel<<<dim3(T_TOK / 128, D_DIM / 128), 256, DN_SMEM>>>(out);
}